// round 2
// baseline (speedup 1.0000x reference)
#include <cuda_runtime.h>
#include <math.h>

#define B_   2
#define C1_  256
#define C2_  256
#define H_   64
#define W_   64
#define HW_  4096
#define OMC  27   // offset(18) + mask(9) channels

// Scratch (device globals — no allocation allowed)
__device__ float g_om[B_ * OMC * HW_];              // offset/mask conv output
__device__ float g_wt[C1_ * 9 * C2_];               // w_dcn transposed: [c][k][o]

// ---------------------------------------------------------------------------
// Kernel 0: transpose w_dcn [o][c][k] -> w_t [c][k][o] for coalesced GEMM loads
// ---------------------------------------------------------------------------
__global__ void transpose_w_kernel(const float* __restrict__ w) {
    int i = blockIdx.x * blockDim.x + threadIdx.x;
    if (i >= C2_ * C1_ * 9) return;
    int k = i % 9;
    int c = (i / 9) % C1_;
    int o = i / (9 * C1_);
    g_wt[(c * 9 + k) * C2_ + o] = w[i];
}

// ---------------------------------------------------------------------------
// Kernel 1: 3x3 conv  offset_feat[2,256,64,64] * w_om[27,256,3,3] + b -> g_om
// Block: one (b, h, 32-wide w strip). 256 threads: oc = tid%32 (27 active),
// pixel-group pg = tid/32 handles 4 pixels.
// ---------------------------------------------------------------------------
__global__ __launch_bounds__(256) void conv_om_kernel(
    const float* __restrict__ in, const float* __restrict__ w,
    const float* __restrict__ bias)
{
    __shared__ float sh[16][3][36];   // 16 in-ch chunk x 3 rows x 34(+pad) cols

    const int bx  = blockIdx.x;
    const int b   = bx >> 7;
    const int h   = (bx & 127) >> 1;
    const int w0  = (bx & 1) * 32;
    const int tid = threadIdx.x;
    const int oc  = tid & 31;
    const int pg  = tid >> 5;

    float acc[4] = {0.f, 0.f, 0.f, 0.f};

    for (int c0 = 0; c0 < C2_; c0 += 16) {
        __syncthreads();
        // cooperative load of 16x3x34 input tile (zero-padded borders)
        for (int t = tid; t < 16 * 3 * 34; t += 256) {
            int c   = t / 102;
            int rem = t - c * 102;
            int r   = rem / 34;
            int col = rem - r * 34;
            int gh = h + r - 1;
            int gw = w0 + col - 1;
            float v = 0.f;
            if (gh >= 0 && gh < H_ && gw >= 0 && gw < W_)
                v = in[((b * C2_ + c0 + c) * H_ + gh) * W_ + gw];
            sh[c][r][col] = v;
        }
        __syncthreads();

        if (oc < OMC) {
            for (int c = 0; c < 16; ++c) {
                const float* wr = w + ((size_t)oc * C2_ + c0 + c) * 9;
                #pragma unroll
                for (int ky = 0; ky < 3; ++ky) {
                    float r6[6];
                    #pragma unroll
                    for (int j = 0; j < 6; ++j) r6[j] = sh[c][ky][pg * 4 + j];
                    #pragma unroll
                    for (int kx = 0; kx < 3; ++kx) {
                        float wv = wr[ky * 3 + kx];
                        #pragma unroll
                        for (int p = 0; p < 4; ++p)
                            acc[p] += wv * r6[p + kx];
                    }
                }
            }
        }
    }

    if (oc < OMC) {
        float bo = bias[oc];
        float* op = g_om + ((size_t)b * OMC + oc) * HW_ + h * W_ + w0 + pg * 4;
        #pragma unroll
        for (int p = 0; p < 4; ++p) op[p] = acc[p] + bo;
    }
}

// ---------------------------------------------------------------------------
// Kernel 2: deformable sampling + GEMM.
// Block: one (b, h, 32-wide w strip) = 32 pixels x all 256 out channels.
// Phase 1: per (pixel,k) compute 4 clamped gather indices + bilinear
//          weights folded with validity and sigmoid(mask).
// Phase 2: loop 32-channel chunks: gather -> shared, then register-blocked
//          GEMM: each thread = 4 out channels x 8 pixels.
// ---------------------------------------------------------------------------
__global__ __launch_bounds__(256) void dcn_kernel(
    const float* __restrict__ x, const float* __restrict__ bias,
    float* __restrict__ out)
{
    __shared__ __align__(16) float val_sh[32][9][32];  // 36 KB
    __shared__ int4   s_idx[288];                      // 4.5 KB
    __shared__ float4 s_w[288];                        // 4.5 KB

    const int bx  = blockIdx.x;
    const int b   = bx >> 7;
    const int h   = (bx & 127) >> 1;
    const int w0  = (bx & 1) * 32;
    const int tid = threadIdx.x;

    // ---- Phase 1: sampling metadata ----
    for (int e = tid; e < 288; e += 256) {
        int p  = e & 31;
        int k  = e >> 5;
        int ky = k / 3;
        int kx = k - ky * 3;
        int wo = w0 + p;
        const float* omb = g_om + (size_t)b * OMC * HW_ + h * W_ + wo;
        float dy = omb[(2 * k) * HW_];
        float dx = omb[(2 * k + 1) * HW_];
        float mv = omb[(18 + k) * HW_];
        float m  = 1.f / (1.f + expf(-mv));

        float ys = (float)(h - 1 + ky) + dy;
        float xs = (float)(wo - 1 + kx) + dx;
        float y0f = floorf(ys), x0f = floorf(xs);
        float ly = ys - y0f, lx = xs - x0f;
        int y0 = (int)y0f, x0 = (int)x0f;
        int y1 = y0 + 1,   x1 = x0 + 1;

        bool vy0 = (y0 >= 0) && (y0 < H_);
        bool vy1 = (y1 >= 0) && (y1 < H_);
        bool vx0 = (x0 >= 0) && (x0 < W_);
        bool vx1 = (x1 >= 0) && (x1 < W_);
        int cy0 = min(max(y0, 0), H_ - 1), cy1 = min(max(y1, 0), H_ - 1);
        int cx0 = min(max(x0, 0), W_ - 1), cx1 = min(max(x1, 0), W_ - 1);

        float w00 = (vy0 && vx0) ? (1.f - ly) * (1.f - lx) * m : 0.f;
        float w01 = (vy0 && vx1) ? (1.f - ly) * lx * m : 0.f;
        float w10 = (vy1 && vx0) ? ly * (1.f - lx) * m : 0.f;
        float w11 = (vy1 && vx1) ? ly * lx * m : 0.f;

        s_idx[e] = make_int4(cy0 * W_ + cx0, cy0 * W_ + cx1,
                             cy1 * W_ + cx0, cy1 * W_ + cx1);
        s_w[e]   = make_float4(w00, w01, w10, w11);
    }
    __syncthreads();

    const int o0 = tid & 63;   // GEMM: out-channel base (o0, +64, +128, +192)
    const int pg = tid >> 6;   // GEMM: pixel group (8 pixels)
    const int gp = tid & 31;   // gather: pixel
    const int gc = tid >> 5;   // gather: channel sub-index (stride 8)

    float acc[4][8];
    #pragma unroll
    for (int j = 0; j < 4; ++j)
        #pragma unroll
        for (int p = 0; p < 8; ++p) acc[j][p] = 0.f;

    for (int c0 = 0; c0 < C1_; c0 += 32) {
        // ---- gather 32 channels x 9 taps x 32 pixels ----
        for (int cc = gc; cc < 32; cc += 8) {
            const float* xp = x + ((size_t)b * C1_ + c0 + cc) * HW_;
            #pragma unroll
            for (int k = 0; k < 9; ++k) {
                int e = k * 32 + gp;
                int4   id = s_idx[e];
                float4 wv = s_w[e];
                float v = wv.x * __ldg(xp + id.x) + wv.y * __ldg(xp + id.y)
                        + wv.z * __ldg(xp + id.z) + wv.w * __ldg(xp + id.w);
                val_sh[cc][k][gp] = v;
            }
        }
        __syncthreads();

        // ---- GEMM: 4 o x 8 p register tile ----
        const float* wtp = g_wt + (size_t)c0 * 9 * C2_ + o0;
        for (int c = 0; c < 32; ++c) {
            #pragma unroll
            for (int k = 0; k < 9; ++k) {
                const float* wp = wtp + (c * 9 + k) * C2_;
                float wv0 = wp[0], wv1 = wp[64], wv2 = wp[128], wv3 = wp[192];
                const float* vp = &val_sh[c][k][pg * 8];
                float4 va = *reinterpret_cast<const float4*>(vp);
                float4 vb = *reinterpret_cast<const float4*>(vp + 4);
                float vv[8] = {va.x, va.y, va.z, va.w, vb.x, vb.y, vb.z, vb.w};
                #pragma unroll
                for (int p = 0; p < 8; ++p) {
                    acc[0][p] += wv0 * vv[p];
                    acc[1][p] += wv1 * vv[p];
                    acc[2][p] += wv2 * vv[p];
                    acc[3][p] += wv3 * vv[p];
                }
            }
        }
        __syncthreads();
    }

    // ---- epilogue ----
    #pragma unroll
    for (int j = 0; j < 4; ++j) {
        int o = o0 + j * 64;
        float bo = bias[o];
        float* op = out + ((size_t)b * C2_ + o) * HW_ + h * W_ + w0 + pg * 8;
        #pragma unroll
        for (int p = 0; p < 8; ++p) op[p] = acc[j][p] + bo;
    }
}

// ---------------------------------------------------------------------------
extern "C" void kernel_launch(void* const* d_in, const int* in_sizes, int n_in,
                              void* d_out, int out_size) {
    const float* x      = (const float*)d_in[0];
    const float* offs   = (const float*)d_in[1];
    const float* w_om   = (const float*)d_in[2];
    const float* b_om   = (const float*)d_in[3];
    const float* w_dcn  = (const float*)d_in[4];
    const float* b_dcn  = (const float*)d_in[5];
    float* out = (float*)d_out;

    transpose_w_kernel<<<(C2_ * C1_ * 9 + 255) / 256, 256>>>(w_dcn);
    conv_om_kernel<<<B_ * H_ * (W_ / 32), 256>>>(offs, w_om, b_om);
    dcn_kernel<<<B_ * H_ * (W_ / 32), 256>>>(x, b_dcn, out);
}

// round 6
// speedup vs baseline: 1.8130x; 1.8130x over previous
#include <cuda_runtime.h>
#include <math.h>

#define B_   2
#define C1_  256
#define C2_  256
#define H_   64
#define W_   64
#define HW_  4096
#define OMC  27   // offset(18) + mask(9) channels

// Scratch (device globals — no allocation allowed)
__device__ float g_om[B_ * OMC * HW_];              // offset/mask conv output
__device__ float g_wt[C1_ * 9 * C2_];               // w_dcn transposed: [c][k][o]

#define N_TRANS_BLK 2304   // transpose blocks (589824 elems / 256)
#define N_CONV_BLK  256    // conv blocks

// f32x2 packed-FMA helpers (sm_100+ PTX; FFMA2 in SASS)
#define BCAST2(dst, s) asm("mov.b64 %0, {%1, %1};" : "=l"(dst) : "f"(s))
#define FFMA2(acc, a, b) \
    asm("fma.rn.f32x2 %0, %1, %2, %0;" : "+l"(acc) : "l"(a), "l"(b))

// ---------------------------------------------------------------------------
// Kernel 1 (merged): blocks [0,2304): transpose w_dcn [o][c][k] -> [c][k][o]
//                    blocks [2304,2560): 3x3 conv offset_feat -> g_om
// ---------------------------------------------------------------------------
__global__ __launch_bounds__(256) void prep_kernel(
    const float* __restrict__ in, const float* __restrict__ w,
    const float* __restrict__ bias, const float* __restrict__ w_dcn)
{
    __shared__ float sh[16][3][36];    // input tile: 16 ch x 3 rows x 34(+2) cols
    __shared__ float wsh[16][27][9];   // weight tile: 16 ch x 27 oc x 9 taps

    const int tid = threadIdx.x;

    if (blockIdx.x < N_TRANS_BLK) {
        int i = blockIdx.x * 256 + tid;   // i < 589824 always
        int k = i % 9;
        int c = (i / 9) % C1_;
        int o = i / (9 * C1_);
        g_wt[(c * 9 + k) * C2_ + o] = w_dcn[i];
        return;
    }

    const int bx  = blockIdx.x - N_TRANS_BLK;
    const int b   = bx >> 7;
    const int h   = (bx & 127) >> 1;
    const int w0  = (bx & 1) * 32;
    const int oc  = tid & 31;
    const int pg  = tid >> 5;

    float acc[4] = {0.f, 0.f, 0.f, 0.f};

    for (int c0 = 0; c0 < C2_; c0 += 16) {
        __syncthreads();
        // input tile 16x3x34 (zero-padded)
        for (int t = tid; t < 16 * 3 * 34; t += 256) {
            int c   = t / 102;
            int rem = t - c * 102;
            int r   = rem / 34;
            int col = rem - r * 34;
            int gh = h + r - 1;
            int gw = w0 + col - 1;
            float v = 0.f;
            if (gh >= 0 && gh < H_ && gw >= 0 && gw < W_)
                v = in[((b * C2_ + c0 + c) * H_ + gh) * W_ + gw];
            sh[c][r][col] = v;
        }
        // weight tile 16x27x9
        for (int t = tid; t < 16 * 27 * 9; t += 256) {
            int c   = t / 243;
            int rem = t - c * 243;
            int o   = rem / 9;
            int k   = rem - o * 9;
            wsh[c][o][k] = w[((size_t)o * C2_ + c0 + c) * 9 + k];
        }
        __syncthreads();

        if (oc < OMC) {
            #pragma unroll 4
            for (int c = 0; c < 16; ++c) {
                #pragma unroll
                for (int ky = 0; ky < 3; ++ky) {
                    float r6[6];
                    #pragma unroll
                    for (int j = 0; j < 6; ++j) r6[j] = sh[c][ky][pg * 4 + j];
                    #pragma unroll
                    for (int kx = 0; kx < 3; ++kx) {
                        float wv = wsh[c][oc][ky * 3 + kx];
                        #pragma unroll
                        for (int p = 0; p < 4; ++p)
                            acc[p] += wv * r6[p + kx];
                    }
                }
            }
        }
    }

    if (oc < OMC) {
        float bo = bias[oc];
        float* op = g_om + ((size_t)b * OMC + oc) * HW_ + h * W_ + w0 + pg * 4;
        #pragma unroll
        for (int p = 0; p < 4; ++p) op[p] = acc[p] + bo;
    }
}

// ---------------------------------------------------------------------------
// Kernel 2: deformable sampling + GEMM (f32x2, weight reg-prefetch depth 2)
// Block: (b, h, 32-wide strip) = 32 px x 256 oc. 256 threads.
// GEMM tile per thread: 4 oc x 8 px (as 4 pixel-pairs).
// ---------------------------------------------------------------------------
__global__ __launch_bounds__(256) void dcn_kernel(
    const float* __restrict__ x, const float* __restrict__ bias,
    float* __restrict__ out)
{
    __shared__ __align__(16) float val_sh[288][32];    // [c*9+k][px]  36 KB
    __shared__ int4   s_idx[288];                      // 4.5 KB
    __shared__ float4 s_w[288];                        // 4.5 KB

    const int bx  = blockIdx.x;
    const int b   = bx >> 7;
    const int h   = (bx & 127) >> 1;
    const int w0  = (bx & 1) * 32;
    const int tid = threadIdx.x;

    // ---- Phase 1: sampling metadata (per pixel x 9 taps) ----
    for (int e = tid; e < 288; e += 256) {
        int p  = e & 31;
        int k  = e >> 5;
        int ky = k / 3;
        int kx = k - ky * 3;
        int wo = w0 + p;
        const float* omb = g_om + (size_t)b * OMC * HW_ + h * W_ + wo;
        float dy = omb[(2 * k) * HW_];
        float dx = omb[(2 * k + 1) * HW_];
        float mv = omb[(18 + k) * HW_];
        float m  = 1.f / (1.f + expf(-mv));

        float ys = (float)(h - 1 + ky) + dy;
        float xs = (float)(wo - 1 + kx) + dx;
        float y0f = floorf(ys), x0f = floorf(xs);
        float ly = ys - y0f, lx = xs - x0f;
        int y0 = (int)y0f, x0 = (int)x0f;
        int y1 = y0 + 1,   x1 = x0 + 1;

        bool vy0 = (y0 >= 0) && (y0 < H_);
        bool vy1 = (y1 >= 0) && (y1 < H_);
        bool vx0 = (x0 >= 0) && (x0 < W_);
        bool vx1 = (x1 >= 0) && (x1 < W_);
        int cy0 = min(max(y0, 0), H_ - 1), cy1 = min(max(y1, 0), H_ - 1);
        int cx0 = min(max(x0, 0), W_ - 1), cx1 = min(max(x1, 0), W_ - 1);

        float w00 = (vy0 && vx0) ? (1.f - ly) * (1.f - lx) * m : 0.f;
        float w01 = (vy0 && vx1) ? (1.f - ly) * lx * m : 0.f;
        float w10 = (vy1 && vx0) ? ly * (1.f - lx) * m : 0.f;
        float w11 = (vy1 && vx1) ? ly * lx * m : 0.f;

        s_idx[e] = make_int4(cy0 * W_ + cx0, cy0 * W_ + cx1,
                             cy1 * W_ + cx0, cy1 * W_ + cx1);
        s_w[e]   = make_float4(w00, w01, w10, w11);
    }
    __syncthreads();

    const int o0 = tid & 63;   // GEMM: out-channel base (o0, +64, +128, +192)
    const int pg = tid >> 6;   // GEMM: pixel-pair group (pixels pg*8..pg*8+7)
    const int gp = tid & 31;   // gather: pixel
    const int gc = tid >> 5;   // gather: channel sub-index (stride 8)

    unsigned long long acc2[4][4];
    #pragma unroll
    for (int j = 0; j < 4; ++j)
        #pragma unroll
        for (int pp = 0; pp < 4; ++pp) acc2[j][pp] = 0ULL;

    for (int c0 = 0; c0 < C1_; c0 += 32) {
        // ---- gather 32 channels x 9 taps x 32 pixels ----
        for (int cc = gc; cc < 32; cc += 8) {
            const float* xp = x + ((size_t)b * C1_ + c0 + cc) * HW_;
            #pragma unroll
            for (int k = 0; k < 9; ++k) {
                int e = k * 32 + gp;
                int4   id = s_idx[e];
                float4 wv = s_w[e];
                float v = wv.x * __ldg(xp + id.x) + wv.y * __ldg(xp + id.y)
                        + wv.z * __ldg(xp + id.z) + wv.w * __ldg(xp + id.w);
                val_sh[cc * 9 + k][gp] = v;
            }
        }
        __syncthreads();

        // ---- GEMM: 288 (c,k) steps, f32x2, depth-2 weight prefetch ----
        const float* wtp = g_wt + (size_t)c0 * 9 * C2_ + o0;
        float4 wa = make_float4(__ldg(wtp +   0), __ldg(wtp +  64),
                                __ldg(wtp + 128), __ldg(wtp + 192));
        const float* wp1 = wtp + C2_;
        float4 wb = make_float4(__ldg(wp1 +   0), __ldg(wp1 +  64),
                                __ldg(wp1 + 128), __ldg(wp1 + 192));

        #pragma unroll 4
        for (int ck = 0; ck < 288; ++ck) {
            float4 wcur = wa;
            wa = wb;
            int nidx = min(ck + 2, 287);
            const float* wpn = wtp + nidx * C2_;
            wb = make_float4(__ldg(wpn +   0), __ldg(wpn +  64),
                             __ldg(wpn + 128), __ldg(wpn + 192));

            const ulonglong2* vp =
                reinterpret_cast<const ulonglong2*>(&val_sh[ck][pg * 8]);
            ulonglong2 v01 = vp[0];
            ulonglong2 v23 = vp[1];
            unsigned long long vv[4] = {v01.x, v01.y, v23.x, v23.y};

            unsigned long long wB0, wB1, wB2, wB3;
            BCAST2(wB0, wcur.x);
            BCAST2(wB1, wcur.y);
            BCAST2(wB2, wcur.z);
            BCAST2(wB3, wcur.w);

            #pragma unroll
            for (int pp = 0; pp < 4; ++pp) {
                FFMA2(acc2[0][pp], wB0, vv[pp]);
                FFMA2(acc2[1][pp], wB1, vv[pp]);
                FFMA2(acc2[2][pp], wB2, vv[pp]);
                FFMA2(acc2[3][pp], wB3, vv[pp]);
            }
        }
        __syncthreads();
    }

    // ---- epilogue ----
    #pragma unroll
    for (int j = 0; j < 4; ++j) {
        int o = o0 + j * 64;
        float bo = bias[o];
        float* op = out + ((size_t)b * C2_ + o) * HW_ + h * W_ + w0 + pg * 8;
        #pragma unroll
        for (int pp = 0; pp < 4; ++pp) {
            float lo, hi;
            asm("mov.b64 {%0, %1}, %2;" : "=f"(lo), "=f"(hi) : "l"(acc2[j][pp]));
            op[pp * 2]     = lo + bo;
            op[pp * 2 + 1] = hi + bo;
        }
    }
}

// ---------------------------------------------------------------------------
extern "C" void kernel_launch(void* const* d_in, const int* in_sizes, int n_in,
                              void* d_out, int out_size) {
    const float* x      = (const float*)d_in[0];
    const float* offs   = (const float*)d_in[1];
    const float* w_om   = (const float*)d_in[2];
    const float* b_om   = (const float*)d_in[3];
    const float* w_dcn  = (const float*)d_in[4];
    const float* b_dcn  = (const float*)d_in[5];
    float* out = (float*)d_out;

    prep_kernel<<<N_TRANS_BLK + N_CONV_BLK, 256>>>(offs, w_om, b_om, w_dcn);
    dcn_kernel<<<B_ * H_ * (W_ / 32), 256>>>(x, b_dcn, out);
}

// round 8
// speedup vs baseline: 2.8157x; 1.5530x over previous
#include <cuda_runtime.h>
#include <math.h>

#define B_   2
#define C1_  256
#define C2_  256
#define H_   64
#define W_   64
#define HW_  4096
#define OMC  27   // offset(18) + mask(9) channels

#define NSPLIT 4            // split-K factor
#define PART_SZ (B_ * C2_ * HW_)

// Scratch (device globals — no allocation allowed)
__device__ float g_om[B_ * OMC * HW_];          // offset/mask conv output
__device__ float g_wt[C1_ * 9 * C2_];           // w_dcn transposed: [c][k][o]
__device__ float g_part[NSPLIT * PART_SZ];      // split-K partials (32 MB)
__device__ int   g_cnt[B_ * H_ * (W_ / 32)];    // per-strip arrival counters (zero-init)

#define N_TRANS_BLK 2304   // transpose blocks (589824 elems / 256)
#define N_CONV_BLK  256    // conv blocks

// f32x2 packed-FMA helpers (sm_100+ PTX; FFMA2 in SASS)
#define BCAST2(dst, s) asm("mov.b64 %0, {%1, %1};" : "=l"(dst) : "f"(s))
#define FFMA2(acc, a, b) \
    asm("fma.rn.f32x2 %0, %1, %2, %0;" : "+l"(acc) : "l"(a), "l"(b))

// ---------------------------------------------------------------------------
// Kernel 1 (merged): blocks [0,2304): transpose w_dcn [o][c][k] -> [c][k][o]
//                    blocks [2304,2560): 3x3 conv offset_feat -> g_om
// ---------------------------------------------------------------------------
__global__ __launch_bounds__(256) void prep_kernel(
    const float* __restrict__ in, const float* __restrict__ w,
    const float* __restrict__ bias, const float* __restrict__ w_dcn)
{
    __shared__ float sh[16][3][36];    // input tile: 16 ch x 3 rows x 34(+2) cols
    __shared__ float wsh[16][27][9];   // weight tile: 16 ch x 27 oc x 9 taps

    const int tid = threadIdx.x;

    if (blockIdx.x < N_TRANS_BLK) {
        int i = blockIdx.x * 256 + tid;   // i < 589824 always
        int k = i % 9;
        int c = (i / 9) % C1_;
        int o = i / (9 * C1_);
        g_wt[(c * 9 + k) * C2_ + o] = w_dcn[i];
        return;
    }

    const int bx  = blockIdx.x - N_TRANS_BLK;
    const int b   = bx >> 7;
    const int h   = (bx & 127) >> 1;
    const int w0  = (bx & 1) * 32;
    const int oc  = tid & 31;
    const int pg  = tid >> 5;

    float acc[4] = {0.f, 0.f, 0.f, 0.f};

    for (int c0 = 0; c0 < C2_; c0 += 16) {
        __syncthreads();
        // input tile 16x3x34 (zero-padded)
        for (int t = tid; t < 16 * 3 * 34; t += 256) {
            int c   = t / 102;
            int rem = t - c * 102;
            int r   = rem / 34;
            int col = rem - r * 34;
            int gh = h + r - 1;
            int gw = w0 + col - 1;
            float v = 0.f;
            if (gh >= 0 && gh < H_ && gw >= 0 && gw < W_)
                v = in[((b * C2_ + c0 + c) * H_ + gh) * W_ + gw];
            sh[c][r][col] = v;
        }
        // weight tile 16x27x9
        for (int t = tid; t < 16 * 27 * 9; t += 256) {
            int c   = t / 243;
            int rem = t - c * 243;
            int o   = rem / 9;
            int k   = rem - o * 9;
            wsh[c][o][k] = w[((size_t)o * C2_ + c0 + c) * 9 + k];
        }
        __syncthreads();

        if (oc < OMC) {
            #pragma unroll 4
            for (int c = 0; c < 16; ++c) {
                #pragma unroll
                for (int ky = 0; ky < 3; ++ky) {
                    float r6[6];
                    #pragma unroll
                    for (int j = 0; j < 6; ++j) r6[j] = sh[c][ky][pg * 4 + j];
                    #pragma unroll
                    for (int kx = 0; kx < 3; ++kx) {
                        float wv = wsh[c][oc][ky * 3 + kx];
                        #pragma unroll
                        for (int p = 0; p < 4; ++p)
                            acc[p] += wv * r6[p + kx];
                    }
                }
            }
        }
    }

    if (oc < OMC) {
        float bo = bias[oc];
        float* op = g_om + ((size_t)b * OMC + oc) * HW_ + h * W_ + w0 + pg * 4;
        #pragma unroll
        for (int p = 0; p < 4; ++p) op[p] = acc[p] + bo;
    }
}

// ---------------------------------------------------------------------------
// Kernel 2: deformable sampling + split-K GEMM + last-block reduction.
// Grid 1024: bx -> strip (b,h,32px) x half (64-channel slice).
// Per block: 32 px x 256 oc over 64 input channels; partial to g_part.
// Last-arriving block of each strip sums 4 partials + bias -> out.
// ---------------------------------------------------------------------------
__global__ __launch_bounds__(256) void dcn_kernel(
    const float* __restrict__ x, const float* __restrict__ bias,
    float* __restrict__ out)
{
    __shared__ __align__(16) float val_sh[288][32];    // [c*9+k][px]  36 KB
    __shared__ int4   s_idx[288];                      // 4.5 KB
    __shared__ float4 s_w[288];                        // 4.5 KB
    __shared__ int    s_last;

    const int bx    = blockIdx.x;
    const int strip = bx >> 2;
    const int half  = bx & 3;
    const int cbase = half * 64;
    const int b     = strip >> 7;
    const int h     = (strip & 127) >> 1;
    const int w0    = (strip & 1) * 32;
    const int tid   = threadIdx.x;

    // ---- Phase 1: sampling metadata (per pixel x 9 taps) ----
    for (int e = tid; e < 288; e += 256) {
        int p  = e & 31;
        int k  = e >> 5;
        int ky = k / 3;
        int kx = k - ky * 3;
        int wo = w0 + p;
        const float* omb = g_om + (size_t)b * OMC * HW_ + h * W_ + wo;
        float dy = omb[(2 * k) * HW_];
        float dx = omb[(2 * k + 1) * HW_];
        float mv = omb[(18 + k) * HW_];
        float m  = 1.f / (1.f + expf(-mv));

        float ys = (float)(h - 1 + ky) + dy;
        float xs = (float)(wo - 1 + kx) + dx;
        float y0f = floorf(ys), x0f = floorf(xs);
        float ly = ys - y0f, lx = xs - x0f;
        int y0 = (int)y0f, x0 = (int)x0f;
        int y1 = y0 + 1,   x1 = x0 + 1;

        bool vy0 = (y0 >= 0) && (y0 < H_);
        bool vy1 = (y1 >= 0) && (y1 < H_);
        bool vx0 = (x0 >= 0) && (x0 < W_);
        bool vx1 = (x1 >= 0) && (x1 < W_);
        int cy0 = min(max(y0, 0), H_ - 1), cy1 = min(max(y1, 0), H_ - 1);
        int cx0 = min(max(x0, 0), W_ - 1), cx1 = min(max(x1, 0), W_ - 1);

        float w00 = (vy0 && vx0) ? (1.f - ly) * (1.f - lx) * m : 0.f;
        float w01 = (vy0 && vx1) ? (1.f - ly) * lx * m : 0.f;
        float w10 = (vy1 && vx0) ? ly * (1.f - lx) * m : 0.f;
        float w11 = (vy1 && vx1) ? ly * lx * m : 0.f;

        s_idx[e] = make_int4(cy0 * W_ + cx0, cy0 * W_ + cx1,
                             cy1 * W_ + cx0, cy1 * W_ + cx1);
        s_w[e]   = make_float4(w00, w01, w10, w11);
    }
    __syncthreads();

    const int o0 = tid & 63;   // out-channel base (o0, +64, +128, +192)
    const int pg = tid >> 6;   // pixel-pair group (pixels pg*8..pg*8+7)
    const int gp = tid & 31;   // gather: pixel
    const int gc = tid >> 5;   // gather: channel sub-index (stride 8)

    unsigned long long acc2[4][4];
    #pragma unroll
    for (int j = 0; j < 4; ++j)
        #pragma unroll
        for (int pp = 0; pp < 4; ++pp) acc2[j][pp] = 0ULL;

    for (int c0 = cbase; c0 < cbase + 64; c0 += 32) {
        // ---- gather 32 channels x 9 taps x 32 pixels ----
        for (int cc = gc; cc < 32; cc += 8) {
            const float* xp = x + ((size_t)b * C1_ + c0 + cc) * HW_;
            #pragma unroll
            for (int k = 0; k < 9; ++k) {
                int e = k * 32 + gp;
                int4   id = s_idx[e];
                float4 wv = s_w[e];
                float v = wv.x * __ldg(xp + id.x) + wv.y * __ldg(xp + id.y)
                        + wv.z * __ldg(xp + id.z) + wv.w * __ldg(xp + id.w);
                val_sh[cc * 9 + k][gp] = v;
            }
        }
        __syncthreads();

        // ---- GEMM: 288 (c,k) steps, f32x2, depth-4 weight prefetch ----
        const float* wtp = g_wt + (size_t)c0 * 9 * C2_ + o0;
        float4 wreg[4];
        #pragma unroll
        for (int d = 0; d < 4; ++d) {
            const float* p = wtp + d * C2_;
            wreg[d] = make_float4(__ldg(p +   0), __ldg(p +  64),
                                  __ldg(p + 128), __ldg(p + 192));
        }

        #pragma unroll 4
        for (int ck = 0; ck < 288; ++ck) {
            float4 wcur = wreg[ck & 3];
            int nidx = ck + 4;
            if (nidx > 287) nidx = 287;
            const float* wpn = wtp + nidx * C2_;
            wreg[ck & 3] = make_float4(__ldg(wpn +   0), __ldg(wpn +  64),
                                       __ldg(wpn + 128), __ldg(wpn + 192));

            const ulonglong2* vp =
                reinterpret_cast<const ulonglong2*>(&val_sh[ck][pg * 8]);
            ulonglong2 v01 = vp[0];
            ulonglong2 v23 = vp[1];
            unsigned long long vv[4] = {v01.x, v01.y, v23.x, v23.y};

            unsigned long long wB0, wB1, wB2, wB3;
            BCAST2(wB0, wcur.x);
            BCAST2(wB1, wcur.y);
            BCAST2(wB2, wcur.z);
            BCAST2(wB3, wcur.w);

            #pragma unroll
            for (int pp = 0; pp < 4; ++pp) {
                FFMA2(acc2[0][pp], wB0, vv[pp]);
                FFMA2(acc2[1][pp], wB1, vv[pp]);
                FFMA2(acc2[2][pp], wB2, vv[pp]);
                FFMA2(acc2[3][pp], wB3, vv[pp]);
            }
        }
        __syncthreads();
    }

    // ---- write partials ----
    #pragma unroll
    for (int j = 0; j < 4; ++j) {
        int o = o0 + j * 64;
        float* op = g_part + (size_t)half * PART_SZ
                  + ((size_t)(b * C2_ + o)) * HW_ + h * W_ + w0 + pg * 8;
        #pragma unroll
        for (int pp = 0; pp < 4; ++pp) {
            float lo, hi;
            asm("mov.b64 {%0, %1}, %2;" : "=f"(lo), "=f"(hi) : "l"(acc2[j][pp]));
            op[pp * 2]     = lo;
            op[pp * 2 + 1] = hi;
        }
    }

    // ---- last-block reduction for this strip ----
    __threadfence();
    __syncthreads();
    if (tid == 0) {
        int old = atomicAdd(&g_cnt[strip], 1);
        s_last = (old == NSPLIT - 1);
        if (old == NSPLIT - 1) g_cnt[strip] = 0;   // reset for next graph replay
    }
    __syncthreads();

    if (s_last) {
        __threadfence();                 // acquire: see other blocks' partials
        const int oc = tid;              // 256 threads = 256 out channels
        const float bo = bias[oc];
        const size_t off = ((size_t)(b * C2_ + oc)) * HW_ + h * W_ + w0;
        #pragma unroll
        for (int px = 0; px < 32; px += 4) {
            float4 s = make_float4(bo, bo, bo, bo);
            #pragma unroll
            for (int sl = 0; sl < NSPLIT; ++sl) {
                float4 v = *reinterpret_cast<const float4*>(
                    g_part + (size_t)sl * PART_SZ + off + px);
                s.x += v.x; s.y += v.y; s.z += v.z; s.w += v.w;
            }
            *reinterpret_cast<float4*>(out + off + px) = s;
        }
    }
}

// ---------------------------------------------------------------------------
extern "C" void kernel_launch(void* const* d_in, const int* in_sizes, int n_in,
                              void* d_out, int out_size) {
    const float* x      = (const float*)d_in[0];
    const float* offs   = (const float*)d_in[1];
    const float* w_om   = (const float*)d_in[2];
    const float* b_om   = (const float*)d_in[3];
    const float* w_dcn  = (const float*)d_in[4];
    const float* b_dcn  = (const float*)d_in[5];
    float* out = (float*)d_out;

    prep_kernel<<<N_TRANS_BLK + N_CONV_BLK, 256>>>(offs, w_om, b_om, w_dcn);
    dcn_kernel<<<B_ * H_ * (W_ / 32) * NSPLIT, 256>>>(x, b_dcn, out);
}

// round 9
// speedup vs baseline: 3.3330x; 1.1837x over previous
#include <cuda_runtime.h>
#include <math.h>

#define B_   2
#define C1_  256
#define C2_  256
#define H_   64
#define W_   64
#define HW_  4096
#define OMC  27   // offset(18) + mask(9) channels

#define NSPLIT 4            // split-K factor (dcn)
#define PART_SZ (B_ * C2_ * HW_)
#define OM_SZ   (B_ * OMC * HW_)

// Scratch (device globals — no allocation allowed)
__device__ float g_om[NSPLIT][OM_SZ];           // offset/mask conv partials
__device__ float g_wt[C1_ * 9 * C2_];           // w_dcn: [(c*9+k)*64+o0][j] float4-packed
__device__ float g_part[NSPLIT * PART_SZ];      // split-K partials (32 MB)
__device__ int   g_cnt[B_ * H_ * (W_ / 32)];    // per-strip arrival counters (zero-init)

#define N_TRANS_BLK 2304   // transpose blocks (589824 elems / 256)
#define N_CONV_BLK  1024   // conv blocks (256 strips x 4 channel slices)

// f32x2 packed-FMA helpers (sm_100+ PTX; FFMA2 in SASS)
#define BCAST2(dst, s) asm("mov.b64 %0, {%1, %1};" : "=l"(dst) : "f"(s))
#define FFMA2(acc, a, b) \
    asm("fma.rn.f32x2 %0, %1, %2, %0;" : "+l"(acc) : "l"(a), "l"(b))

// ---------------------------------------------------------------------------
// Kernel 1 (merged): blocks [0,2304): permute w_dcn [o][c][k] ->
//                    g_wt[((c*9+k)*64 + (o&63))*4 + (o>>6)]
//                    blocks [2304,3328): 3x3 conv offset_feat -> g_om partials
//                    (strip x 4 channel slices of 64; slice 0 adds bias)
// ---------------------------------------------------------------------------
__global__ __launch_bounds__(256) void prep_kernel(
    const float* __restrict__ in, const float* __restrict__ w,
    const float* __restrict__ bias, const float* __restrict__ w_dcn)
{
    __shared__ float sh[16][3][36];    // input tile: 16 ch x 3 rows x 34(+2) cols
    __shared__ float wsh[16][27][9];   // weight tile: 16 ch x 27 oc x 9 taps

    const int tid = threadIdx.x;

    if (blockIdx.x < N_TRANS_BLK) {
        int i = blockIdx.x * 256 + tid;   // i < 589824 always
        int k = i % 9;
        int c = (i / 9) % C1_;
        int o = i / (9 * C1_);
        g_wt[((c * 9 + k) * 64 + (o & 63)) * 4 + (o >> 6)] = w_dcn[i];
        return;
    }

    const int bx    = blockIdx.x - N_TRANS_BLK;
    const int strip = bx >> 2;
    const int slice = bx & 3;
    const int b     = strip >> 7;
    const int h     = (strip & 127) >> 1;
    const int w0    = (strip & 1) * 32;
    const int oc    = tid & 31;
    const int pg    = tid >> 5;

    float acc[4] = {0.f, 0.f, 0.f, 0.f};

    for (int c0 = slice * 64; c0 < slice * 64 + 64; c0 += 16) {
        __syncthreads();
        // input tile 16x3x34 (zero-padded)
        for (int t = tid; t < 16 * 3 * 34; t += 256) {
            int c   = t / 102;
            int rem = t - c * 102;
            int r   = rem / 34;
            int col = rem - r * 34;
            int gh = h + r - 1;
            int gw = w0 + col - 1;
            float v = 0.f;
            if (gh >= 0 && gh < H_ && gw >= 0 && gw < W_)
                v = in[((b * C2_ + c0 + c) * H_ + gh) * W_ + gw];
            sh[c][r][col] = v;
        }
        // weight tile 16x27x9
        for (int t = tid; t < 16 * 27 * 9; t += 256) {
            int c   = t / 243;
            int rem = t - c * 243;
            int o   = rem / 9;
            int k   = rem - o * 9;
            wsh[c][o][k] = w[((size_t)o * C2_ + c0 + c) * 9 + k];
        }
        __syncthreads();

        if (oc < OMC) {
            #pragma unroll 4
            for (int c = 0; c < 16; ++c) {
                #pragma unroll
                for (int ky = 0; ky < 3; ++ky) {
                    float r6[6];
                    #pragma unroll
                    for (int j = 0; j < 6; ++j) r6[j] = sh[c][ky][pg * 4 + j];
                    #pragma unroll
                    for (int kx = 0; kx < 3; ++kx) {
                        float wv = wsh[c][oc][ky * 3 + kx];
                        #pragma unroll
                        for (int p = 0; p < 4; ++p)
                            acc[p] += wv * r6[p + kx];
                    }
                }
            }
        }
    }

    if (oc < OMC) {
        float bo = (slice == 0) ? bias[oc] : 0.f;
        float* op = g_om[slice] + ((size_t)b * OMC + oc) * HW_ + h * W_ + w0 + pg * 4;
        #pragma unroll
        for (int p = 0; p < 4; ++p) op[p] = acc[p] + bo;
    }
}

// ---------------------------------------------------------------------------
// Kernel 2: deformable sampling + split-K GEMM + last-block reduction.
// Grid 1024: bx -> strip (b,h,32px) x quarter (64-channel slice).
// Phase 1 sums the 4 offset-conv partials. GEMM weight load = 1 LDG.128/step.
// ---------------------------------------------------------------------------
__global__ __launch_bounds__(256) void dcn_kernel(
    const float* __restrict__ x, const float* __restrict__ bias,
    float* __restrict__ out)
{
    __shared__ __align__(16) float val_sh[288][32];    // [c*9+k][px]  36 KB
    __shared__ int4   s_idx[288];                      // 4.5 KB
    __shared__ float4 s_w[288];                        // 4.5 KB
    __shared__ int    s_last;

    const int bx    = blockIdx.x;
    const int strip = bx >> 2;
    const int half  = bx & 3;
    const int cbase = half * 64;
    const int b     = strip >> 7;
    const int h     = (strip & 127) >> 1;
    const int w0    = (strip & 1) * 32;
    const int tid   = threadIdx.x;

    // ---- Phase 1: sampling metadata (per pixel x 9 taps) ----
    for (int e = tid; e < 288; e += 256) {
        int p  = e & 31;
        int k  = e >> 5;
        int ky = k / 3;
        int kx = k - ky * 3;
        int wo = w0 + p;
        const size_t base = (size_t)b * OMC * HW_ + h * W_ + wo;
        float dy = 0.f, dx = 0.f, mv = 0.f;
        #pragma unroll
        for (int s = 0; s < NSPLIT; ++s) {
            const float* omb = g_om[s] + base;
            dy += omb[(2 * k) * HW_];
            dx += omb[(2 * k + 1) * HW_];
            mv += omb[(18 + k) * HW_];
        }
        float m  = 1.f / (1.f + expf(-mv));

        float ys = (float)(h - 1 + ky) + dy;
        float xs = (float)(wo - 1 + kx) + dx;
        float y0f = floorf(ys), x0f = floorf(xs);
        float ly = ys - y0f, lx = xs - x0f;
        int y0 = (int)y0f, x0 = (int)x0f;
        int y1 = y0 + 1,   x1 = x0 + 1;

        bool vy0 = (y0 >= 0) && (y0 < H_);
        bool vy1 = (y1 >= 0) && (y1 < H_);
        bool vx0 = (x0 >= 0) && (x0 < W_);
        bool vx1 = (x1 >= 0) && (x1 < W_);
        int cy0 = min(max(y0, 0), H_ - 1), cy1 = min(max(y1, 0), H_ - 1);
        int cx0 = min(max(x0, 0), W_ - 1), cx1 = min(max(x1, 0), W_ - 1);

        float w00 = (vy0 && vx0) ? (1.f - ly) * (1.f - lx) * m : 0.f;
        float w01 = (vy0 && vx1) ? (1.f - ly) * lx * m : 0.f;
        float w10 = (vy1 && vx0) ? ly * (1.f - lx) * m : 0.f;
        float w11 = (vy1 && vx1) ? ly * lx * m : 0.f;

        s_idx[e] = make_int4(cy0 * W_ + cx0, cy0 * W_ + cx1,
                             cy1 * W_ + cx0, cy1 * W_ + cx1);
        s_w[e]   = make_float4(w00, w01, w10, w11);
    }
    __syncthreads();

    const int o0 = tid & 63;   // out-channel base (o0, +64, +128, +192)
    const int pg = tid >> 6;   // pixel-pair group (pixels pg*8..pg*8+7)
    const int gp = tid & 31;   // gather: pixel
    const int gc = tid >> 5;   // gather: channel sub-index (stride 8)

    unsigned long long acc2[4][4];
    #pragma unroll
    for (int j = 0; j < 4; ++j)
        #pragma unroll
        for (int pp = 0; pp < 4; ++pp) acc2[j][pp] = 0ULL;

    for (int c0 = cbase; c0 < cbase + 64; c0 += 32) {
        // ---- gather 32 channels x 9 taps x 32 pixels ----
        for (int cc = gc; cc < 32; cc += 8) {
            const float* xp = x + ((size_t)b * C1_ + c0 + cc) * HW_;
            #pragma unroll
            for (int k = 0; k < 9; ++k) {
                int e = k * 32 + gp;
                int4   id = s_idx[e];
                float4 wv = s_w[e];
                float v = wv.x * __ldg(xp + id.x) + wv.y * __ldg(xp + id.y)
                        + wv.z * __ldg(xp + id.z) + wv.w * __ldg(xp + id.w);
                val_sh[cc * 9 + k][gp] = v;
            }
        }
        __syncthreads();

        // ---- GEMM: 288 (c,k) steps, f32x2, LDG.128 weights, depth-4 ring ----
        const float4* wq = reinterpret_cast<const float4*>(g_wt)
                         + (size_t)c0 * 9 * 64 + o0;
        float4 wreg[4];
        #pragma unroll
        for (int d = 0; d < 4; ++d) wreg[d] = __ldg(wq + d * 64);

        #pragma unroll 4
        for (int ck = 0; ck < 288; ++ck) {
            float4 wcur = wreg[ck & 3];
            int nidx = ck + 4;
            if (nidx > 287) nidx = 287;
            wreg[ck & 3] = __ldg(wq + nidx * 64);

            const ulonglong2* vp =
                reinterpret_cast<const ulonglong2*>(&val_sh[ck][pg * 8]);
            ulonglong2 v01 = vp[0];
            ulonglong2 v23 = vp[1];
            unsigned long long vv[4] = {v01.x, v01.y, v23.x, v23.y};

            unsigned long long wB0, wB1, wB2, wB3;
            BCAST2(wB0, wcur.x);
            BCAST2(wB1, wcur.y);
            BCAST2(wB2, wcur.z);
            BCAST2(wB3, wcur.w);

            #pragma unroll
            for (int pp = 0; pp < 4; ++pp) {
                FFMA2(acc2[0][pp], wB0, vv[pp]);
                FFMA2(acc2[1][pp], wB1, vv[pp]);
                FFMA2(acc2[2][pp], wB2, vv[pp]);
                FFMA2(acc2[3][pp], wB3, vv[pp]);
            }
        }
        __syncthreads();
    }

    // ---- write partials ----
    #pragma unroll
    for (int j = 0; j < 4; ++j) {
        int o = o0 + j * 64;
        float* op = g_part + (size_t)half * PART_SZ
                  + ((size_t)(b * C2_ + o)) * HW_ + h * W_ + w0 + pg * 8;
        #pragma unroll
        for (int pp = 0; pp < 4; ++pp) {
            float lo, hi;
            asm("mov.b64 {%0, %1}, %2;" : "=f"(lo), "=f"(hi) : "l"(acc2[j][pp]));
            op[pp * 2]     = lo;
            op[pp * 2 + 1] = hi;
        }
    }

    // ---- last-block reduction for this strip ----
    __threadfence();
    __syncthreads();
    if (tid == 0) {
        int old = atomicAdd(&g_cnt[strip], 1);
        s_last = (old == NSPLIT - 1);
        if (old == NSPLIT - 1) g_cnt[strip] = 0;   // reset for next graph replay
    }
    __syncthreads();

    if (s_last) {
        __threadfence();                 // acquire: see other blocks' partials
        const int oc = tid;              // 256 threads = 256 out channels
        const float bo = bias[oc];
        const size_t off = ((size_t)(b * C2_ + oc)) * HW_ + h * W_ + w0;
        #pragma unroll
        for (int px = 0; px < 32; px += 4) {
            float4 s = make_float4(bo, bo, bo, bo);
            #pragma unroll
            for (int sl = 0; sl < NSPLIT; ++sl) {
                float4 v = *reinterpret_cast<const float4*>(
                    g_part + (size_t)sl * PART_SZ + off + px);
                s.x += v.x; s.y += v.y; s.z += v.z; s.w += v.w;
            }
            *reinterpret_cast<float4*>(out + off + px) = s;
        }
    }
}

// ---------------------------------------------------------------------------
extern "C" void kernel_launch(void* const* d_in, const int* in_sizes, int n_in,
                              void* d_out, int out_size) {
    const float* x      = (const float*)d_in[0];
    const float* offs   = (const float*)d_in[1];
    const float* w_om   = (const float*)d_in[2];
    const float* b_om   = (const float*)d_in[3];
    const float* w_dcn  = (const float*)d_in[4];
    const float* b_dcn  = (const float*)d_in[5];
    float* out = (float*)d_out;

    prep_kernel<<<N_TRANS_BLK + N_CONV_BLK, 256>>>(offs, w_om, b_om, w_dcn);
    dcn_kernel<<<B_ * H_ * (W_ / 32) * NSPLIT, 256>>>(x, b_dcn, out);
}